// round 17
// baseline (speedup 1.0000x reference)
#include <cuda_runtime.h>
#include <cuda_fp16.h>
#include <cstdint>

#define SEQ_LEN  120
#define BATCH    2048
#define INPUT    6
#define HID      64
#define GATES    256
#define LAYERS   4
#define TLEN     120
#define NB       16
#define NCTA     (BATCH / NB)   // 128
#define NTHR     512            // 16 warps: 1 m-tile each

#define KP       136            // B row pitch in halves
#define NSLOT    5
#define SLOT_B   32768
#define CPS      16             // 4 chunks per layer: hiA,hiB,loA,loB
#define TOTALC   (240 * CPS)
#define PHASE_HALVES 237568     // (4*20480 + 12*32768)/2

typedef unsigned long long ull;

__device__ __half g_hs_e[PHASE_HALVES];
__device__ __half g_hs_d[PHASE_HALVES];

__host__ __device__ __forceinline__ int chunk_off_h(int c) {
    return (c < 4) ? c * 10240 : 40960 + (c - 4) * 16384;
}

// fragment-order pack (identical to R16)
__global__ void lstm36206574305735_pack(
    const float* __restrict__ eW0, const float* __restrict__ eWih,
    const float* __restrict__ eWhh, const float* __restrict__ dW0,
    const float* __restrict__ dWih, const float* __restrict__ dWhh)
{
    const int tot = 2 * PHASE_HALVES;
    for (int idx = blockIdx.x * blockDim.x + threadIdx.x; idx < tot;
         idx += gridDim.x * blockDim.x) {
        int p   = idx / PHASE_HALVES;
        int hix = idx % PHASE_HALVES;
        int c, e, KS;
        if (hix < 40960) { c = hix / 10240; e = hix % 10240; KS = 5; }
        else { int r2 = hix - 40960; c = 4 + r2 / 16384; e = r2 % 16384; KS = 8; }
        int l = c >> 2, q = c & 3;
        int mtl = e / (KS * 256);
        int rem = e % (KS * 256);
        int ks  = rem / 256;
        int le  = rem & 255;
        int lane = le >> 3;
        int ri   = le & 7;
        int mt = (q & 1) * 8 + mtl;
        int rg = ri >> 1, hl = ri & 1;
        int row = mt * 16 + (lane >> 2) + ((rg & 1) ? 8 : 0);
        int kk  = ks * 16 + (lane & 3) * 2 + ((rg & 2) ? 8 : 0) + hl;
        const float* W0  = p ? dW0  : eW0;
        const float* Wih = p ? dWih : eWih;
        const float* Whh = p ? dWhh : eWhh;
        float w = 0.0f;
        if (l == 0) {
            if (kk < 16) { if (kk < INPUT) w = W0[row * INPUT + kk]; }
            else w = Whh[row * HID + (kk - 16)];
        } else {
            if (kk < 64) w = Wih[((size_t)(l - 1) * GATES + row) * HID + kk];
            else         w = Whh[((size_t)l * GATES + row) * HID + (kk - 64)];
        }
        __half hi = __float2half(w);
        __half v  = (q < 2) ? hi : __float2half(w - __half2float(hi));
        (p ? g_hs_d : g_hs_e)[chunk_off_h(c) + e] = v;
    }
}

// ---- helpers ----------------------------------------------------------------
__device__ __forceinline__ float tanha(float x) {
    float y; asm("tanh.approx.f32 %0, %1;" : "=f"(y) : "f"(x)); return y;
}
__device__ __forceinline__ float fsig(float x) {
    return fmaf(0.5f, tanha(0.5f * x), 0.5f);
}
__device__ __forceinline__ uint32_t smem_u32(const void* p) {
    uint32_t a;
    asm("{ .reg .u64 t; cvta.to.shared.u64 t, %1; cvt.u32.u64 %0, t; }"
        : "=r"(a) : "l"(p));
    return a;
}
__device__ __forceinline__ void wait_parity(uint32_t mb, uint32_t parity) {
    asm volatile(
        "{\n\t"
        ".reg .pred P;\n\t"
        "WLOOP_%=:\n\t"
        "mbarrier.try_wait.parity.acquire.cta.shared::cta.b64 P, [%0], %1, 0x989680;\n\t"
        "@P bra WDONE_%=;\n\t"
        "bra WLOOP_%=;\n\t"
        "WDONE_%=:\n\t"
        "}"
        :: "r"(mb), "r"(parity) : "memory");
}
__device__ __forceinline__ void hmma(float acc[4], const uint32_t a[4],
                                     uint32_t b0, uint32_t b1) {
    asm volatile(
        "mma.sync.aligned.m16n8k16.row.col.f32.f16.f16.f32 "
        "{%0,%1,%2,%3}, {%4,%5,%6,%7}, {%8,%9}, {%0,%1,%2,%3};"
        : "+f"(acc[0]), "+f"(acc[1]), "+f"(acc[2]), "+f"(acc[3])
        : "r"(a[0]), "r"(a[1]), "r"(a[2]), "r"(a[3]), "r"(b0), "r"(b1));
}

// ---- smem layout (bytes) ------------------------------------------------------
#define RING_SZ  (NSLOT * SLOT_B)          // 163840
#define BH_B     RING_SZ                   // __half [4][16][KP]
#define BL_B     (BH_B + 4 * 16 * KP * 2)
#define SB_B     (BL_B + 4 * 16 * KP * 2)  // f32 [256][20]
#define BIAS_B   (SB_B + 256 * 20 * 4)
#define LW_B     (BIAS_B + 8192)
#define LB_B     (LW_B + 1536)
#define MBAR_B   (LB_B + 32)
#define SMEM_TOTAL_B 228944

__global__ void __launch_bounds__(NTHR, 1)
lstm36206574305735_main(const float* __restrict__ x,
                        const float* __restrict__ eB,
                        const float* __restrict__ dB,
                        const float* __restrict__ linW,
                        const float* __restrict__ linB,
                        float* __restrict__ out)
{
    extern __shared__ char sm[];
    const uint32_t base_u = smem_u32(sm);
    const uint32_t mbar_u = base_u + MBAR_B;
    __half* BH   = (__half*)(sm + BH_B);
    __half* BL   = (__half*)(sm + BL_B);
    float* sbuf  = (float*)(sm + SB_B);
    float* bias_s = (float*)(sm + BIAS_B);
    float* lw_s  = (float*)(sm + LW_B);
    float* lb_s  = (float*)(sm + LB_B);

    const int tid  = threadIdx.x;
    const int w    = tid >> 5;        // 0..15, m-tile index
    const int lane = tid & 31;
    const int hh   = tid >> 3;        // 0..63 (epilogue hid)
    const int bq   = tid & 7;         // batch pair index (2 batch each)
    const int b0   = blockIdx.x * NB;

    if (tid == 0) {
        for (int s = 0; s < NSLOT; s++)
            asm volatile("mbarrier.init.shared.b64 [%0], 1;"
                         :: "r"(mbar_u + s * 8) : "memory");
        asm volatile("fence.proxy.async.shared::cta;" ::: "memory");
    }
    for (int i = tid; i < (2 * 4 * 16 * KP * 2) / 4; i += NTHR)
        ((uint32_t*)(sm + BH_B))[i] = 0u;
    for (int u = tid; u < 2 * LAYERS * GATES; u += NTHR) {
        int p = u / (LAYERS * GATES), r = u % (LAYERS * GATES);
        bias_s[u] = (p ? dB : eB)[r];
    }
    for (int i = tid; i < HID * INPUT; i += NTHR) {
        int h2 = i / INPUT, ii2 = i % INPUT;
        lw_s[h2 * INPUT + ii2] = linW[ii2 * HID + h2];
    }
    if (tid < INPUT) lb_s[tid] = linB[tid];
    __syncthreads();

    auto issue_one = [&](int G) {
        if (G >= TOTALC) return;
        int s = G % NSLOT;
        int cc = G % CPS;
        const __half* src = ((G < 120 * CPS) ? g_hs_e : g_hs_d) + chunk_off_h(cc);
        uint32_t bytes = (cc < 4) ? 20480u : 32768u;
        uint32_t mb = mbar_u + s * 8;
        asm volatile("mbarrier.arrive.expect_tx.shared.b64 _, [%0], %1;"
                     :: "r"(mb), "r"(bytes) : "memory");
        asm volatile("cp.async.bulk.shared::cluster.global.mbarrier::complete_tx::bytes "
                     "[%0], [%1], %2, [%3];"
                     :: "r"(base_u + (uint32_t)s * SLOT_B), "l"(src),
                        "r"(bytes), "r"(mb) : "memory");
    };
    auto lw = [&](int G) {
        if (G >= TOTALC) return;
        wait_parity(mbar_u + (G % NSLOT) * 8, (uint32_t)((G / NSLOT) & 1));
    };
    if (tid == 0)
        for (int g = 0; g < NSLOT; g++) issue_one(g);
    int Gi = NSLOT;

    float c_reg[LAYERS][2];
#pragma unroll
    for (int l = 0; l < LAYERS; l++) {
        c_reg[l][0] = 0.0f; c_reg[l][1] = 0.0f;
    }

    const int  bb  = tid / INPUT;
    const int  ii  = tid % INPUT;
    const bool isx = tid < INPUT * NB;
    float xreg = 0.0f;
    if (isx) xreg = x[(size_t)(b0 + bb) * INPUT + ii];

    const int nb = lane >> 2;          // B frag n within 8-col tile
    const int kb = (lane & 3) * 2;     // B frag k base
    const int mtl = w & 7;             // m-tile within chunk half
    int G = 0;

    for (int t = 0; t < SEQ_LEN + TLEN; t++) {
        const int p = (t >= SEQ_LEN) ? 1 : 0;

        if (t < SEQ_LEN && isx) {
            __half hi = __float2half(xreg);
            __half lo = __float2half(xreg - __half2float(hi));
            BH[bb * KP + ii] = hi;
            BL[bb * KP + ii] = lo;
            if (t + 1 < SEQ_LEN)
                xreg = x[((size_t)(t + 1) * BATCH + b0 + bb) * INPUT + ii];
        }

#pragma unroll
        for (int l = 0; l < LAYERS; l++) {
            const int KS = (l == 0) ? 5 : 8;

            if (tid == 0) { lw(G); lw(G + 1); lw(G + 2); lw(G + 3); }
            __syncthreads();

            // ---- MMA: one m-tile per warp (warps 0-7: chunk q0/q2, 8-15: q1/q3)
            const char* slotHi = sm + (size_t)((G + (w >> 3)) % NSLOT) * SLOT_B;
            const char* slotLo = sm + (size_t)((G + 2 + (w >> 3)) % NSLOT) * SLOT_B;
            const __half* BhL = BH + l * 16 * KP;
            const __half* BlL = BL + l * 16 * KP;

            float acc[2][4];
#pragma unroll
            for (int ni = 0; ni < 2; ni++)
#pragma unroll
                for (int q = 0; q < 4; q++) acc[ni][q] = 0.0f;

            for (int ks = 0; ks < KS; ks++) {
                uint32_t bh[2][2], bl[2][2];
#pragma unroll
                for (int ni = 0; ni < 2; ni++) {
                    int nrow = ni * 8 + nb;
                    int k0 = ks * 16 + kb;
                    bh[ni][0] = *(const uint32_t*)&BhL[nrow * KP + k0];
                    bh[ni][1] = *(const uint32_t*)&BhL[nrow * KP + k0 + 8];
                    bl[ni][0] = *(const uint32_t*)&BlL[nrow * KP + k0];
                    bl[ni][1] = *(const uint32_t*)&BlL[nrow * KP + k0 + 8];
                }
                const uint32_t* ah = (const uint32_t*)
                    (slotHi + ((size_t)(mtl * KS + ks) * 32 + lane) * 16);
                const uint32_t* al = (const uint32_t*)
                    (slotLo + ((size_t)(mtl * KS + ks) * 32 + lane) * 16);
                uint32_t ahr[4] = {ah[0], ah[1], ah[2], ah[3]};
                uint32_t alr[4] = {al[0], al[1], al[2], al[3]};
#pragma unroll
                for (int ni = 0; ni < 2; ni++) {
                    hmma(acc[ni], ahr, bh[ni][0], bh[ni][1]);
                    hmma(acc[ni], ahr, bl[ni][0], bl[ni][1]);
                    hmma(acc[ni], alr, bh[ni][0], bh[ni][1]);
                }
            }

            // ---- store gates to sbuf [256 rows][20]
            {
                int row0 = w * 16 + (lane >> 2);
#pragma unroll
                for (int ni = 0; ni < 2; ni++) {
                    int col = ni * 8 + (lane & 3) * 2;
                    *(float2*)&sbuf[row0 * 20 + col] =
                        make_float2(acc[ni][0], acc[ni][1]);
                    *(float2*)&sbuf[(row0 + 8) * 20 + col] =
                        make_float2(acc[ni][2], acc[ni][3]);
                }
            }
            __syncthreads();
            if (tid == 0) { issue_one(Gi); issue_one(Gi + 1); issue_one(Gi + 2); issue_one(Gi + 3); }
            Gi += 4;

            // ---- cell epilogue: 512 threads, each (hid, 2 batch)
            {
                float2 zi2 = *(float2*)&sbuf[(0 * HID + hh) * 20 + bq * 2];
                float2 zf2 = *(float2*)&sbuf[(1 * HID + hh) * 20 + bq * 2];
                float2 zg2 = *(float2*)&sbuf[(2 * HID + hh) * 20 + bq * 2];
                float2 zo2 = *(float2*)&sbuf[(3 * HID + hh) * 20 + bq * 2];
                float b_i = bias_s[(p * LAYERS + l) * GATES + 0 * HID + hh];
                float b_f = bias_s[(p * LAYERS + l) * GATES + 1 * HID + hh];
                float b_g = bias_s[(p * LAYERS + l) * GATES + 2 * HID + hh];
                float b_o = bias_s[(p * LAYERS + l) * GATES + 3 * HID + hh];
                float zi[2] = {zi2.x, zi2.y};
                float zf[2] = {zf2.x, zf2.y};
                float zg[2] = {zg2.x, zg2.y};
                float zo[2] = {zo2.x, zo2.y};
                int koff_own = ((l == 0) ? 16 : 64) + hh;
#pragma unroll
                for (int bi = 0; bi < 2; bi++) {
                    int n = bq * 2 + bi;
                    float c = fmaf(fsig(zf[bi] + b_f), c_reg[l][bi],
                                   fsig(zi[bi] + b_i) * tanha(zg[bi] + b_g));
                    c_reg[l][bi] = c;
                    float hv = fsig(zo[bi] + b_o) * tanha(c);
                    __half hi = __float2half(hv);
                    __half lo = __float2half(hv - __half2float(hi));
                    BH[(l * 16 + n) * KP + koff_own] = hi;
                    BL[(l * 16 + n) * KP + koff_own] = lo;
                    if (l < 3) {
                        BH[((l + 1) * 16 + n) * KP + hh] = hi;
                        BL[((l + 1) * 16 + n) * KP + hh] = lo;
                    }
                }
            }
            __syncthreads();
            G += 4;
        }

        // ---- decoder projection + feedback
        if (t >= SEQ_LEN && isx) {
            const __half* bh3 = BH + (3 * 16 + bb) * KP + 64;
            const __half* bl3 = BL + (3 * 16 + bb) * KP + 64;
            float v = lb_s[ii];
#pragma unroll 8
            for (int h4 = 0; h4 < HID; h4++)
                v += lw_s[h4 * INPUT + ii]
                     * (__half2float(bh3[h4]) + __half2float(bl3[h4]));
            out[((size_t)(t - SEQ_LEN) * BATCH + b0 + bb) * INPUT + ii] = v;
            __half hi = __float2half(v);
            __half lo = __float2half(v - __half2float(hi));
            BH[bb * KP + ii] = hi;
            BL[bb * KP + ii] = lo;
        }
        // ordered before next step's L0 MMA by the L0 entry __syncthreads
    }
}

extern "C" void kernel_launch(void* const* d_in, const int* in_sizes, int n_in,
                              void* d_out, int out_size)
{
    const float* x    = (const float*)d_in[0];
    const float* eW0  = (const float*)d_in[1];
    const float* eWih = (const float*)d_in[2];
    const float* eWhh = (const float*)d_in[3];
    const float* eB   = (const float*)d_in[4];
    const float* dW0  = (const float*)d_in[5];
    const float* dWih = (const float*)d_in[6];
    const float* dWhh = (const float*)d_in[7];
    const float* dB   = (const float*)d_in[8];
    const float* linW = (const float*)d_in[9];
    const float* linB = (const float*)d_in[10];
    float* out = (float*)d_out;

    lstm36206574305735_pack<<<464, 256>>>(eW0, eWih, eWhh, dW0, dWih, dWhh);

    cudaFuncSetAttribute(lstm36206574305735_main,
                         cudaFuncAttributeMaxDynamicSharedMemorySize, SMEM_TOTAL_B);
    lstm36206574305735_main<<<NCTA, NTHR, SMEM_TOTAL_B>>>(x, eB, dB, linW, linB, out);
}